// round 6
// baseline (speedup 1.0000x reference)
#include <cuda_runtime.h>
#include <cuda_bf16.h>

// SpatialTransformer: 3D trilinear grid-sample, border padding, align_corners=True.
// img [2,1,160,192,224], flow [2,3,160,192,224], out [2,1,160,192,224].
//
// px = (x + flow0 + 1)*0.5*223 clamps to 223 for ~98% of voxels (fx = 0) -> bilinear
// on the x=223 border slice, precomputed CORNER-PACKED:
//   bs4[b][z][y] = (s[z][y], s[z][y1], s[z1][y], s[z1][y1])  (clamps baked in)
// so the fast path is ONE aligned LDG.128 + 6 flops.
// R6: 1 output/thread, <=32 regs -> 64 warps/SM (full occupancy) to hide the
// flow-load -> gather dependency chain. Streaming hints protect the slice in L2.

#define DD 160
#define HH 192
#define WW 224
#define HW (HH * WW)
#define NVOX (DD * HH * WW)   // 6,881,280
#define NB 2
#define NSLICE (NB * DD * HH) // 61,440

__device__ float4 g_bs4[NSLICE];   // corner-packed border slice

__global__ __launch_bounds__(256) void build_bs4_kernel(
    const float* __restrict__ img)
{
    int idx = blockIdx.x * blockDim.x + threadIdx.x;
    if (idx >= NSLICE) return;
    int b = idx / (DD * HH);
    int r = idx - b * (DD * HH);      // z*HH + y
    int z = r / HH;
    int y = r - z * HH;
    int y1 = min(y + 1, HH - 1);
    int z1 = min(z + 1, DD - 1);

    const float* im = img + (size_t)b * NVOX + (WW - 1);
    float4 v;
    v.x = __ldg(im + (size_t)z  * HW + y  * WW);
    v.y = __ldg(im + (size_t)z  * HW + y1 * WW);
    v.z = __ldg(im + (size_t)z1 * HW + y  * WW);
    v.w = __ldg(im + (size_t)z1 * HW + y1 * WW);
    g_bs4[idx] = v;
}

__global__ __launch_bounds__(256, 8) void st3d_kernel(
    const float* __restrict__ img,
    const float* __restrict__ flow,
    float* __restrict__ out)
{
    // NB*NVOX = 13,762,560 is an exact multiple of 256 -> no bounds check.
    const int idx = blockIdx.x * blockDim.x + threadIdx.x;
    const int b = (idx >= NVOX) ? 1 : 0;
    const int i = idx - b * NVOX;

    const int z = i / HW;
    const int rem = i - z * HW;
    const int y = rem / WW;
    const int x = rem - y * WW;

    const float* fb = flow + (size_t)b * 3 * NVOX;

    // 3 coalesced scalar streaming loads (flow read exactly once)
    const float f0 = __ldcs(fb + i);
    const float f1 = __ldcs(fb + NVOX + i);
    const float f2 = __ldcs(fb + 2 * NVOX + i);

    // raw px (before clamp); *0.5f*223.0f == *111.5f bitwise (0.5*223 exact)
    const float pxr = ((float)x + f0 + 1.0f) * 111.5f;

    float py = (float)y + f1;
    float pz = (float)z + f2;
    py = fminf(fmaxf(py, 0.0f), (float)(HH - 1));
    pz = fminf(fmaxf(pz, 0.0f), (float)(DD - 1));

    const float y0f = floorf(py);
    const float z0f = floorf(pz);
    const float fy = py - y0f;
    const float fz = pz - z0f;
    const int y0 = (int)y0f;
    const int z0 = (int)z0f;

    float res;
    if (pxr >= (float)(WW - 1)) {
        // border fast path: fx == 0; all 4 corners in one packed LDG.128
        const float4 v = __ldg(g_bs4 + b * (DD * HH) + z0 * HH + y0);
        const float c0 = v.x + (v.y - v.x) * fy;
        const float c1 = v.z + (v.w - v.z) * fy;
        res = c0 + (c1 - c0) * fz;
    } else {
        const float* im = img + (size_t)b * NVOX;
        const float px = fmaxf(pxr, 0.0f);      // px < 223 here
        const float x0f = floorf(px);
        const float fx = px - x0f;
        const int x0 = (int)x0f;
        const int x1 = min(x0 + 1, WW - 1);
        const int y1 = min(y0 + 1, HH - 1);
        const int z1 = min(z0 + 1, DD - 1);

        const long long zb0 = (long long)z0 * HW;
        const long long zb1 = (long long)z1 * HW;
        const int yb0 = y0 * WW;
        const int yb1 = y1 * WW;

        const float c000 = __ldg(im + zb0 + yb0 + x0);
        const float c001 = __ldg(im + zb0 + yb0 + x1);
        const float c010 = __ldg(im + zb0 + yb1 + x0);
        const float c011 = __ldg(im + zb0 + yb1 + x1);
        const float c100 = __ldg(im + zb1 + yb0 + x0);
        const float c101 = __ldg(im + zb1 + yb0 + x1);
        const float c110 = __ldg(im + zb1 + yb1 + x0);
        const float c111 = __ldg(im + zb1 + yb1 + x1);

        const float c00 = c000 + (c001 - c000) * fx;
        const float c01 = c010 + (c011 - c010) * fx;
        const float c10 = c100 + (c101 - c100) * fx;
        const float c11 = c110 + (c111 - c110) * fx;
        const float c0 = c00 + (c01 - c00) * fy;
        const float c1 = c10 + (c11 - c10) * fy;
        res = c0 + (c1 - c0) * fz;
    }

    __stcs(out + idx, res);
}

extern "C" void kernel_launch(void* const* d_in, const int* in_sizes, int n_in,
                              void* d_out, int out_size)
{
    const float* img  = (const float*)d_in[0];
    const float* flow = (const float*)d_in[1];
    float* out = (float*)d_out;

    build_bs4_kernel<<<(NSLICE + 255) / 256, 256>>>(img);

    const int threads = 256;
    const int blocks = (NB * NVOX) / threads;   // 53,760 (exact)
    st3d_kernel<<<blocks, threads>>>(img, flow, out);
}